// round 2
// baseline (speedup 1.0000x reference)
#include <cuda_runtime.h>

// Problem shapes (fixed by the dataset).
constexpr int Bb = 16;
constexpr int Kk = 128;
constexpr int Nn = 8192;
constexpr int Mm = Nn + Kk;   // 8320

// Output packing: tuple concatenated in return order, all float32.
constexpr size_t OFF_ROIS = 0;
constexpr size_t OFF_LAB  = (size_t)Bb * Mm * 5;               // 665600
constexpr size_t OFF_TGT  = OFF_LAB + (size_t)Bb * Mm;         // 798720
constexpr size_t OFF_IW   = OFF_TGT + (size_t)Bb * Mm * 4;     // 1331200
constexpr size_t OFF_OW   = OFF_IW  + (size_t)Bb * Mm * 4;     // 1863680

// Scratch (no allocations allowed -> __device__ globals).
__device__ float g_maxov[Bb * Mm];
__device__ int   g_assign[Bb * Mm];
__device__ int   g_dest[Bb * Mm];

// ---------------------------------------------------------------------------
// Kernel 1: per-roi IoU max/argmax over K gt boxes (division-free mainloop),
// plus focal inside/outside weights in ORIGINAL roi order.
// ---------------------------------------------------------------------------
__global__ __launch_bounds__(256) void k_iou(const float* __restrict__ rois,
                                             const float* __restrict__ gt,
                                             float* __restrict__ out) {
    const int b = blockIdx.y;
    const int m = blockIdx.x * 256 + threadIdx.x;

    __shared__ float sx1[Kk], sy1[Kk], sx2[Kk], sy2[Kk], sar[Kk];
    __shared__ int   szf[Kk];

    const float* gtb = gt + (size_t)b * Kk * 5;
    for (int k = threadIdx.x; k < Kk; k += 256) {
        float x1 = gtb[k * 5 + 0], y1 = gtb[k * 5 + 1];
        float x2 = gtb[k * 5 + 2], y2 = gtb[k * 5 + 3];
        float w = x2 - x1 + 1.0f, h = y2 - y1 + 1.0f;
        sx1[k] = x1; sy1[k] = y1; sx2[k] = x2; sy2[k] = y2;
        sar[k] = w * h;
        szf[k] = (w == 1.0f && h == 1.0f) ? 1 : 0;
    }
    __syncthreads();
    if (m >= Mm) return;

    float x1, y1, x2, y2;
    if (m < Nn) {
        const float* r = rois + ((size_t)b * Nn + m) * 5;
        x1 = r[1]; y1 = r[2]; x2 = r[3]; y2 = r[4];
    } else {
        const float* r = gtb + (size_t)(m - Nn) * 5;
        x1 = r[0]; y1 = r[1]; x2 = r[2]; y2 = r[3];
    }
    const float aw = x2 - x1 + 1.0f;
    const float ah = y2 - y1 + 1.0f;
    const float areaA = aw * ah;
    const bool anz = (aw == 1.0f) && (ah == 1.0f);

    // ov = inter/den; track (bi, bd) of running best; compare via cross-mult
    // (den > 0 always). Init (bi=-1, bd=1) == ov=-1 so k=0 always wins first.
    float bi = -1.0f, bd = 1.0f;
    int arg = 0;
    #pragma unroll 4
    for (int k = 0; k < Kk; ++k) {
        float ix1 = fmaxf(x1, sx1[k]);
        float iy1 = fmaxf(y1, sy1[k]);
        float ix2 = fminf(x2, sx2[k]);
        float iy2 = fminf(y2, sy2[k]);
        float iw = fmaxf(ix2 - ix1 + 1.0f, 0.0f);
        float ih = fmaxf(iy2 - iy1 + 1.0f, 0.0f);
        float inter = iw * ih;
        if (szf[k]) inter = 0.0f;   // zero-area gt forces ov = 0
        float den = areaA + sar[k] - inter;
        if (inter * bd > bi * den) { bi = inter; bd = den; arg = k; }
    }

    float mo;
    if (anz) { mo = -1.0f; arg = 0; }     // zero-area roi: all ov = -1, argmax = 0
    else     { mo = bi / bd; }            // one exact div: matches jax rounding

    const int idx = b * Mm + m;
    g_maxov[idx]  = mo;
    g_assign[idx] = arg;

    const bool fg = mo >= 0.5f;
    const float om = 1.0f - mo;
    const float w  = fg ? om * om : 0.0f;
    const float ow = (w > 0.0f) ? 1.0f : 0.0f;
    ((float4*)(out + OFF_IW))[idx] = make_float4(w, w, w, w);
    ((float4*)(out + OFF_OW))[idx] = make_float4(ow, ow, ow, ow);
}

// ---------------------------------------------------------------------------
// Kernel 2: per-batch stable-partition destination indices (block scan).
// ---------------------------------------------------------------------------
__global__ __launch_bounds__(1024) void k_scan() {
    const int b = blockIdx.x;
    const int tid = threadIdx.x;
    const int lane = tid & 31, wid = tid >> 5;
    __shared__ int ws[32];
    __shared__ int s_run;
    __shared__ int s_tot;

    // Pass 1: total fg count in this batch.
    int loc = 0;
    for (int m = tid; m < Mm; m += 1024)
        loc += (g_maxov[b * Mm + m] >= 0.5f) ? 1 : 0;
    #pragma unroll
    for (int o = 16; o > 0; o >>= 1) loc += __shfl_down_sync(0xffffffffu, loc, o);
    if (lane == 0) ws[wid] = loc;
    __syncthreads();
    if (tid < 32) {
        int v = ws[tid];
        #pragma unroll
        for (int o = 16; o > 0; o >>= 1) v += __shfl_down_sync(0xffffffffu, v, o);
        if (tid == 0) { s_tot = v; s_run = 0; }
    }
    __syncthreads();
    const int tot = s_tot;

    // Pass 2: chunked exclusive prefix sum of fg flags -> dest indices.
    for (int base = 0; base < Mm; base += 1024) {
        const int m = base + tid;
        const int f = (m < Mm && g_maxov[b * Mm + m] >= 0.5f) ? 1 : 0;
        int v = f;
        #pragma unroll
        for (int o = 1; o < 32; o <<= 1) {
            int n = __shfl_up_sync(0xffffffffu, v, o);
            if (lane >= o) v += n;
        }
        if (lane == 31) ws[wid] = v;
        __syncthreads();
        if (tid < 32) {
            int w = ws[tid];
            #pragma unroll
            for (int o = 1; o < 32; o <<= 1) {
                int n = __shfl_up_sync(0xffffffffu, w, o);
                if (tid >= o) w += n;
            }
            ws[tid] = w;
        }
        __syncthreads();
        const int excl = v - f + (wid ? ws[wid - 1] : 0) + s_run;  // fg before m
        const int ct = ws[31];
        if (m < Mm)
            g_dest[b * Mm + m] = f ? excl : (tot + (m - excl));
        __syncthreads();
        if (tid == 0) s_run += ct;
        __syncthreads();
    }
}

// ---------------------------------------------------------------------------
// Kernel 3: scatter rois/labels + bbox_transform targets (full-grid).
// ---------------------------------------------------------------------------
__global__ __launch_bounds__(256) void k_scatter(const float* __restrict__ rois,
                                                 const float* __restrict__ gt,
                                                 float* __restrict__ out) {
    const int b = blockIdx.y;
    const int m = blockIdx.x * 256 + threadIdx.x;
    if (m >= Mm) return;
    const int idx = b * Mm + m;
    const float mo = g_maxov[idx];
    const int a = g_assign[idx];
    const int d = g_dest[idx];
    const bool fg = mo >= 0.5f;

    float x1, y1, x2, y2;
    if (m < Nn) {
        const float* r = rois + ((size_t)b * Nn + m) * 5;
        x1 = r[1]; y1 = r[2]; x2 = r[3]; y2 = r[4];
    } else {
        const float* r = gt + ((size_t)b * Kk + (m - Nn)) * 5;
        x1 = r[0]; y1 = r[1]; x2 = r[2]; y2 = r[3];
    }

    float* rb = out + OFF_ROIS + ((size_t)b * Mm + d) * 5;
    rb[0] = (float)b; rb[1] = x1; rb[2] = y1; rb[3] = x2; rb[4] = y2;

    const float* gb = gt + ((size_t)b * Kk + a) * 5;
    out[OFF_LAB + (size_t)b * Mm + d] = fg ? gb[4] : 0.0f;  // labels in {1..3} -> fg <=> label>0

    float t0 = 0.0f, t1 = 0.0f, t2 = 0.0f, t3 = 0.0f;
    if (fg) {
        float ew = x2 - x1 + 1.0f, eh = y2 - y1 + 1.0f;
        float ecx = x1 + 0.5f * ew, ecy = y1 + 0.5f * eh;
        float gw = gb[2] - gb[0] + 1.0f, gh = gb[3] - gb[1] + 1.0f;
        float gcx = gb[0] + 0.5f * gw, gcy = gb[1] + 0.5f * gh;
        t0 = ((gcx - ecx) / ew) / 0.1f;
        t1 = ((gcy - ecy) / eh) / 0.1f;
        t2 = logf(gw / ew) / 0.2f;
        t3 = logf(gh / eh) / 0.2f;
    }
    ((float4*)(out + OFF_TGT))[(size_t)b * Mm + d] = make_float4(t0, t1, t2, t3);
}

extern "C" void kernel_launch(void* const* d_in, const int* in_sizes, int n_in,
                              void* d_out, int out_size) {
    const float* rois = (const float*)d_in[0];   // (B, N, 5)
    const float* gt   = (const float*)d_in[1];   // (B, K, 5)
    float* out = (float*)d_out;

    dim3 grid((Mm + 255) / 256, Bb);
    k_iou<<<grid, 256>>>(rois, gt, out);
    k_scan<<<Bb, 1024>>>();
    k_scatter<<<grid, 256>>>(rois, gt, out);
}

// round 4
// speedup vs baseline: 1.3253x; 1.3253x over previous
#include <cuda_runtime.h>

// Problem shapes (fixed by the dataset).
constexpr int Bb = 16;
constexpr int Kk = 128;
constexpr int Nn = 8192;
constexpr int Mm = Nn + Kk;   // 8320
constexpr int Ww = Mm / 32;   // 260 bitmask words per batch (8320 % 32 == 0)

// Output packing: tuple concatenated in return order, all float32.
constexpr size_t OFF_ROIS = 0;
constexpr size_t OFF_LAB  = (size_t)Bb * Mm * 5;
constexpr size_t OFF_TGT  = OFF_LAB + (size_t)Bb * Mm;
constexpr size_t OFF_IW   = OFF_TGT + (size_t)Bb * Mm * 4;
constexpr size_t OFF_OW   = OFF_IW  + (size_t)Bb * Mm * 4;

// Scratch (no allocations allowed -> __device__ globals).
__device__ int      g_assign[Bb * Mm];
__device__ unsigned g_mask[Bb * Ww];
__device__ int      g_woff[Bb * Ww];
__device__ int      g_fgtot[Bb];

// ---------------------------------------------------------------------------
// Kernel 1: per-roi IoU max/argmax over K gt boxes. 2 rois per thread to
// amortize smem loads; division-free comparator inter_k*S_b > bI*S_k
// (monotone-equivalent since ov = r/(1-r), r = inter/S). Also emits focal
// weights (original order) and the fg bitmask.
// ---------------------------------------------------------------------------
__global__ __launch_bounds__(128) void k_iou(const float* __restrict__ rois,
                                             const float* __restrict__ gt,
                                             float* __restrict__ out) {
    const int b = blockIdx.y;
    const int t = threadIdx.x;
    const int base = blockIdx.x * 256;
    const int m0 = base + t;          // always < Mm (grid sized so)
    const int m1 = m0 + 128;
    const bool v1 = (m1 < Mm);

    __shared__ float4 sc[Kk];   // gx1, gy1, gx2 (or -1e30 if zero-area), gy2
    __shared__ float  ssar[Kk]; // gt area (w*h) -- exactly 1.0 for zero-area

    const float* gtb = gt + (size_t)b * Kk * 5;
    {
        const int k = t;  // 128 threads == Kk
        float x1 = gtb[k * 5 + 0], y1 = gtb[k * 5 + 1];
        float x2 = gtb[k * 5 + 2], y2 = gtb[k * 5 + 3];
        float w = x2 - x1 + 1.0f, h = y2 - y1 + 1.0f;
        bool zf = (w == 1.0f) && (h == 1.0f);
        sc[k] = make_float4(x1, y1, zf ? -1e30f : x2, y2);
        ssar[k] = w * h;
    }
    __syncthreads();

    float ax1, ay1, ax2, ay2, bx1, by1, bx2, by2;
    {
        if (m0 < Nn) { const float* r = rois + ((size_t)b * Nn + m0) * 5;
                       ax1 = r[1]; ay1 = r[2]; ax2 = r[3]; ay2 = r[4]; }
        else         { const float* r = gtb + (size_t)(m0 - Nn) * 5;
                       ax1 = r[0]; ay1 = r[1]; ax2 = r[2]; ay2 = r[3]; }
        const int mm = v1 ? m1 : m0;
        if (mm < Nn) { const float* r = rois + ((size_t)b * Nn + mm) * 5;
                       bx1 = r[1]; by1 = r[2]; bx2 = r[3]; by2 = r[4]; }
        else         { const float* r = gtb + (size_t)(mm - Nn) * 5;
                       bx1 = r[0]; by1 = r[1]; bx2 = r[2]; by2 = r[3]; }
    }
    const float aw0 = ax2 - ax1 + 1.0f, ah0 = ay2 - ay1 + 1.0f;
    const float aw1 = bx2 - bx1 + 1.0f, ah1 = by2 - by1 + 1.0f;
    const float aA0 = aw0 * ah0, aA1 = aw1 * ah1;

    float bI0 = 0.0f, bS0 = 1.0f, bI1 = 0.0f, bS1 = 1.0f;
    int a0 = 0, a1 = 0;
    #pragma unroll 4
    for (int k = 0; k < Kk; ++k) {
        const float4 c = sc[k];
        const float sa = ssar[k];
        {
            float iw = fmaxf(fminf(ax2, c.z) - fmaxf(ax1, c.x) + 1.0f, 0.0f);
            float ih = fmaxf(fminf(ay2, c.w) - fmaxf(ay1, c.y) + 1.0f, 0.0f);
            float in0 = iw * ih;
            float S = aA0 + sa;
            if (in0 * bS0 > bI0 * S) { bI0 = in0; bS0 = S; a0 = k; }
        }
        {
            float iw = fmaxf(fminf(bx2, c.z) - fmaxf(bx1, c.x) + 1.0f, 0.0f);
            float ih = fmaxf(fminf(by2, c.w) - fmaxf(by1, c.y) + 1.0f, 0.0f);
            float in1 = iw * ih;
            float S = aA1 + sa;
            if (in1 * bS1 > bI1 * S) { bI1 = in1; bS1 = S; a1 = k; }
        }
    }

    // Final ratios: den = S_b - bI is the reference's exact expression.
    float mo0, mo1;
    if ((aw0 == 1.0f) && (ah0 == 1.0f)) { mo0 = -1.0f; a0 = 0; }
    else                                { mo0 = bI0 / (bS0 - bI0); }
    if ((aw1 == 1.0f) && (ah1 == 1.0f)) { mo1 = -1.0f; a1 = 0; }
    else                                { mo1 = bI1 / (bS1 - bI1); }

    const bool fg0 = mo0 >= 0.5f;
    const bool fg1 = v1 && (mo1 >= 0.5f);
    const unsigned bal0 = __ballot_sync(0xffffffffu, fg0);
    const unsigned bal1 = __ballot_sync(0xffffffffu, fg1);

    {
        const int idx = b * Mm + m0;
        g_assign[idx] = a0;
        const float om = 1.0f - mo0;
        const float w = fg0 ? om * om : 0.0f;
        const float ow = (w > 0.0f) ? 1.0f : 0.0f;
        ((float4*)(out + OFF_IW))[idx] = make_float4(w, w, w, w);
        ((float4*)(out + OFF_OW))[idx] = make_float4(ow, ow, ow, ow);
    }
    if (v1) {
        const int idx = b * Mm + m1;
        g_assign[idx] = a1;
        const float om = 1.0f - mo1;
        const float w = fg1 ? om * om : 0.0f;
        const float ow = (w > 0.0f) ? 1.0f : 0.0f;
        ((float4*)(out + OFF_IW))[idx] = make_float4(w, w, w, w);
        ((float4*)(out + OFF_OW))[idx] = make_float4(ow, ow, ow, ow);
    }
    if ((t & 31) == 0) {
        g_mask[b * Ww + (m0 >> 5)] = bal0;
        if (v1) g_mask[b * Ww + (m1 >> 5)] = bal1;   // warp-uniform validity
    }
}

// ---------------------------------------------------------------------------
// Kernel 2: per-batch exclusive scan of per-word fg popcounts (260 words).
// ---------------------------------------------------------------------------
__global__ __launch_bounds__(256) void k_scan() {
    const int b = blockIdx.x;
    const int t = threadIdx.x;
    const int lane = t & 31, wid = t >> 5;
    __shared__ int ws[8];

    const int w0 = 2 * t, w1 = 2 * t + 1;
    int c0 = (w0 < Ww) ? __popc(g_mask[b * Ww + w0]) : 0;
    int c1 = (w1 < Ww) ? __popc(g_mask[b * Ww + w1]) : 0;
    const int s = c0 + c1;

    int v = s;
    #pragma unroll
    for (int o = 1; o < 32; o <<= 1) {
        int n = __shfl_up_sync(0xffffffffu, v, o);
        if (lane >= o) v += n;
    }
    if (lane == 31) ws[wid] = v;
    __syncthreads();
    if (t < 8) {
        int x = ws[t];
        #pragma unroll
        for (int o = 1; o < 8; o <<= 1) {
            int n = __shfl_up_sync(0x000000ffu, x, o);
            if (t >= o) x += n;
        }
        ws[t] = x;
    }
    __syncthreads();
    const int excl = v - s + (wid ? ws[wid - 1] : 0);
    if (w0 < Ww) g_woff[b * Ww + w0] = excl;
    if (w1 < Ww) g_woff[b * Ww + w1] = excl + c0;
    if (t == 0) g_fgtot[b] = ws[7];
}

// ---------------------------------------------------------------------------
// Kernel 3: scatter rois/labels + bbox_transform targets. Dest index is
// recovered from the fg bitmask (warp-uniform word load) + word offsets.
// ---------------------------------------------------------------------------
__global__ __launch_bounds__(256) void k_scatter(const float* __restrict__ rois,
                                                 const float* __restrict__ gt,
                                                 float* __restrict__ out) {
    const int b = blockIdx.y;
    const int m = blockIdx.x * 256 + threadIdx.x;
    if (m >= Mm) return;

    const int word = m >> 5, bit = m & 31;
    const unsigned mask = g_mask[b * Ww + word];
    const int woff = g_woff[b * Ww + word];
    const int pre = woff + __popc(mask & ((1u << bit) - 1u));  // fg before m
    const bool fg = (mask >> bit) & 1u;
    const int tot = g_fgtot[b];
    const int d = fg ? pre : tot + (m - pre);
    const int a = g_assign[b * Mm + m];

    float x1, y1, x2, y2;
    if (m < Nn) {
        const float* r = rois + ((size_t)b * Nn + m) * 5;
        x1 = r[1]; y1 = r[2]; x2 = r[3]; y2 = r[4];
    } else {
        const float* r = gt + ((size_t)b * Kk + (m - Nn)) * 5;
        x1 = r[0]; y1 = r[1]; x2 = r[2]; y2 = r[3];
    }

    float* rb = out + OFF_ROIS + ((size_t)b * Mm + d) * 5;
    rb[0] = (float)b; rb[1] = x1; rb[2] = y1; rb[3] = x2; rb[4] = y2;

    const float* gb = gt + ((size_t)b * Kk + a) * 5;
    out[OFF_LAB + (size_t)b * Mm + d] = fg ? gb[4] : 0.0f;  // labels in {1..3}

    float t0 = 0.0f, t1 = 0.0f, t2 = 0.0f, t3 = 0.0f;
    if (fg) {
        float ew = x2 - x1 + 1.0f, eh = y2 - y1 + 1.0f;
        float ecx = x1 + 0.5f * ew, ecy = y1 + 0.5f * eh;
        float gw = gb[2] - gb[0] + 1.0f, gh = gb[3] - gb[1] + 1.0f;
        float gcx = gb[0] + 0.5f * gw, gcy = gb[1] + 0.5f * gh;
        t0 = ((gcx - ecx) / ew) / 0.1f;
        t1 = ((gcy - ecy) / eh) / 0.1f;
        t2 = logf(gw / ew) / 0.2f;
        t3 = logf(gh / eh) / 0.2f;
    }
    ((float4*)(out + OFF_TGT))[(size_t)b * Mm + d] = make_float4(t0, t1, t2, t3);
}

extern "C" void kernel_launch(void* const* d_in, const int* in_sizes, int n_in,
                              void* d_out, int out_size) {
    const float* rois = (const float*)d_in[0];   // (B, N, 5)
    const float* gt   = (const float*)d_in[1];   // (B, K, 5)
    float* out = (float*)d_out;

    dim3 grid_iou((Mm + 255) / 256, Bb);     // 33 x 16 blocks of 128 (2 rois/thr)
    k_iou<<<grid_iou, 128>>>(rois, gt, out);
    k_scan<<<Bb, 256>>>();
    dim3 grid_sc((Mm + 255) / 256, Bb);
    k_scatter<<<grid_sc, 256>>>(rois, gt, out);
}

// round 7
// speedup vs baseline: 1.3269x; 1.0013x over previous
#include <cuda_runtime.h>

// Problem shapes (fixed by the dataset).
constexpr int Bb = 16;
constexpr int Kk = 128;
constexpr int Nn = 8192;
constexpr int Mm = Nn + Kk;   // 8320
constexpr int Ww = Mm / 32;   // 260 bitmask words per batch

// Output packing: tuple concatenated in return order, all float32.
constexpr size_t OFF_ROIS = 0;
constexpr size_t OFF_LAB  = (size_t)Bb * Mm * 5;
constexpr size_t OFF_TGT  = OFF_LAB + (size_t)Bb * Mm;
constexpr size_t OFF_IW   = OFF_TGT + (size_t)Bb * Mm * 4;
constexpr size_t OFF_OW   = OFF_IW  + (size_t)Bb * Mm * 4;

// Scratch (no allocations allowed -> __device__ globals).
__device__ int      g_assign[Bb * Mm];
__device__ unsigned g_mask[Bb * Ww];
__device__ int      g_woff[Bb * Ww];
__device__ int      g_fgtot[Bb];

// ---------------------------------------------------------------------------
// Kernel 1: per-roi IoU max/argmax over K gt boxes. 4 rois/thread (ILP=4,
// LDS amortized), +1 folded into precomputed x2+1/y2+1 on both sides,
// division-free comparator inter_k*S_b > bI*S_k (ov = r/(1-r) monotone in
// r = inter/S). Appended-gt self-pairs are resolved analytically in the
// epilogue (ov==1 exactly in the reference), so no inner-loop exactness is
// required. Emits focal weights (original order) + fg bitmask.
// ---------------------------------------------------------------------------
__global__ __launch_bounds__(256) void k_iou(const float* __restrict__ rois,
                                             const float* __restrict__ gt,
                                             float* __restrict__ out) {
    const int b = blockIdx.y;
    const int t = threadIdx.x;
    const int base = blockIdx.x * 1024;

    __shared__ float4 sc[Kk];   // gx1, gy1, gx2+1 (or -1e30 if zero-area), gy2+1
    __shared__ float  ssar[Kk]; // gt area (reference expression)

    const float* gtb = gt + (size_t)b * Kk * 5;
    if (t < Kk) {
        float x1 = gtb[t * 5 + 0], y1 = gtb[t * 5 + 1];
        float x2 = gtb[t * 5 + 2], y2 = gtb[t * 5 + 3];
        float w = x2 - x1 + 1.0f, h = y2 - y1 + 1.0f;
        bool zf = (w == 1.0f) && (h == 1.0f);
        sc[t] = make_float4(x1, y1, zf ? -1e30f : (x2 + 1.0f), y2 + 1.0f);
        ssar[t] = w * h;
    }
    __syncthreads();

    int   m[4]; bool val[4];
    float X1[4], Y1[4], X2p[4], Y2p[4], AA[4], AW[4], AH[4];
    #pragma unroll
    for (int r = 0; r < 4; ++r) {
        m[r] = base + r * 256 + t;
        val[r] = (m[r] < Mm);
        const int mm = val[r] ? m[r] : (Mm - 1);
        float x1, y1, x2, y2;
        if (mm < Nn) { const float* p = rois + ((size_t)b * Nn + mm) * 5;
                       x1 = p[1]; y1 = p[2]; x2 = p[3]; y2 = p[4]; }
        else         { const float* p = gtb + (size_t)(mm - Nn) * 5;
                       x1 = p[0]; y1 = p[1]; x2 = p[2]; y2 = p[3]; }
        AW[r] = x2 - x1 + 1.0f;
        AH[r] = y2 - y1 + 1.0f;
        AA[r] = AW[r] * AH[r];
        X1[r] = x1; Y1[r] = y1; X2p[r] = x2 + 1.0f; Y2p[r] = y2 + 1.0f;
    }

    float bI[4] = {0.f, 0.f, 0.f, 0.f};
    float bS[4] = {1.f, 1.f, 1.f, 1.f};
    int   arg[4] = {0, 0, 0, 0};

    #pragma unroll 4
    for (int k = 0; k < Kk; ++k) {
        const float4 c = sc[k];
        const float sa = ssar[k];
        #pragma unroll
        for (int r = 0; r < 4; ++r) {
            float iw = fmaxf(fminf(X2p[r], c.z) - fmaxf(X1[r], c.x), 0.0f);
            float ih = fmaxf(fminf(Y2p[r], c.w) - fmaxf(Y1[r], c.y), 0.0f);
            float in_ = iw * ih;
            float S = AA[r] + sa;
            if (in_ * bS[r] > bI[r] * S) { bI[r] = in_; bS[r] = S; arg[r] = k; }
        }
    }

    #pragma unroll
    for (int r = 0; r < 4; ++r) {
        float mo; int a = arg[r]; bool fg;
        if ((AW[r] == 1.0f) && (AH[r] == 1.0f)) {          // zero-area roi
            mo = -1.0f; fg = false; a = 0;
        } else if (m[r] >= Nn) {                           // appended gt: ov==1 exactly
            mo = 1.0f; fg = true; a = m[r] - Nn;
        } else {
            mo = bI[r] / (bS[r] - bI[r]);
            fg = (mo >= 0.5f);
        }
        fg = fg && val[r];
        const unsigned bal = __ballot_sync(0xffffffffu, fg);
        if (val[r]) {
            const int idx = b * Mm + m[r];
            if (fg) g_assign[idx] = a;
            const float om = 1.0f - mo;
            const float w = fg ? om * om : 0.0f;
            const float ow = (w > 0.0f) ? 1.0f : 0.0f;
            ((float4*)(out + OFF_IW))[idx] = make_float4(w, w, w, w);
            ((float4*)(out + OFF_OW))[idx] = make_float4(ow, ow, ow, ow);
            if ((t & 31) == 0) g_mask[b * Ww + (m[r] >> 5)] = bal;
        }
    }
}

// ---------------------------------------------------------------------------
// Kernel 2: per-batch exclusive scan of per-word fg popcounts (260 words).
// ---------------------------------------------------------------------------
__global__ __launch_bounds__(256) void k_scan() {
    const int b = blockIdx.x;
    const int t = threadIdx.x;
    const int lane = t & 31, wid = t >> 5;
    __shared__ int ws[8];

    const int w0 = 2 * t, w1 = 2 * t + 1;
    int c0 = (w0 < Ww) ? __popc(g_mask[b * Ww + w0]) : 0;
    int c1 = (w1 < Ww) ? __popc(g_mask[b * Ww + w1]) : 0;
    const int s = c0 + c1;

    int v = s;
    #pragma unroll
    for (int o = 1; o < 32; o <<= 1) {
        int n = __shfl_up_sync(0xffffffffu, v, o);
        if (lane >= o) v += n;
    }
    if (lane == 31) ws[wid] = v;
    __syncthreads();
    if (t < 8) {
        int x = ws[t];
        #pragma unroll
        for (int o = 1; o < 8; o <<= 1) {
            int n = __shfl_up_sync(0x000000ffu, x, o);
            if (t >= o) x += n;
        }
        ws[t] = x;
    }
    __syncthreads();
    const int excl = v - s + (wid ? ws[wid - 1] : 0);
    if (w0 < Ww) g_woff[b * Ww + w0] = excl;
    if (w1 < Ww) g_woff[b * Ww + w1] = excl + c0;
    if (t == 0) g_fgtot[b] = ws[7];
}

// ---------------------------------------------------------------------------
// Kernel 3: scatter rois/labels + bbox_transform targets. Dest recovered
// from the fg bitmask + word offsets; g_assign read only for fg rois.
// ---------------------------------------------------------------------------
__global__ __launch_bounds__(256) void k_scatter(const float* __restrict__ rois,
                                                 const float* __restrict__ gt,
                                                 float* __restrict__ out) {
    const int b = blockIdx.y;
    const int m = blockIdx.x * 256 + threadIdx.x;
    if (m >= Mm) return;

    const int word = m >> 5, bit = m & 31;
    const unsigned mask = g_mask[b * Ww + word];
    const int woff = g_woff[b * Ww + word];
    const int pre = woff + __popc(mask & ((1u << bit) - 1u));  // fg before m
    const bool fg = (mask >> bit) & 1u;
    const int tot = g_fgtot[b];
    const int d = fg ? pre : tot + (m - pre);

    float x1, y1, x2, y2;
    if (m < Nn) {
        const float* r = rois + ((size_t)b * Nn + m) * 5;
        x1 = r[1]; y1 = r[2]; x2 = r[3]; y2 = r[4];
    } else {
        const float* r = gt + ((size_t)b * Kk + (m - Nn)) * 5;
        x1 = r[0]; y1 = r[1]; x2 = r[2]; y2 = r[3];
    }

    float* rb = out + OFF_ROIS + ((size_t)b * Mm + d) * 5;
    rb[0] = (float)b; rb[1] = x1; rb[2] = y1; rb[3] = x2; rb[4] = y2;

    float lab = 0.0f;
    float t0 = 0.0f, t1 = 0.0f, t2 = 0.0f, t3 = 0.0f;
    if (fg) {
        const int a = g_assign[b * Mm + m];
        const float* gb = gt + ((size_t)b * Kk + a) * 5;
        lab = gb[4];                                 // labels in {1..3}
        float ew = x2 - x1 + 1.0f, eh = y2 - y1 + 1.0f;
        float ecx = x1 + 0.5f * ew, ecy = y1 + 0.5f * eh;
        float gw = gb[2] - gb[0] + 1.0f, gh = gb[3] - gb[1] + 1.0f;
        float gcx = gb[0] + 0.5f * gw, gcy = gb[1] + 0.5f * gh;
        t0 = ((gcx - ecx) / ew) / 0.1f;
        t1 = ((gcy - ecy) / eh) / 0.1f;
        t2 = logf(gw / ew) / 0.2f;
        t3 = logf(gh / eh) / 0.2f;
    }
    out[OFF_LAB + (size_t)b * Mm + d] = lab;
    ((float4*)(out + OFF_TGT))[(size_t)b * Mm + d] = make_float4(t0, t1, t2, t3);
}

extern "C" void kernel_launch(void* const* d_in, const int* in_sizes, int n_in,
                              void* d_out, int out_size) {
    const float* rois = (const float*)d_in[0];   // (B, N, 5)
    const float* gt   = (const float*)d_in[1];   // (B, K, 5)
    float* out = (float*)d_out;

    dim3 grid_iou((Mm + 1023) / 1024, Bb);       // 9 x 16 = 144 blocks, 4 rois/thr
    k_iou<<<grid_iou, 256>>>(rois, gt, out);
    k_scan<<<Bb, 256>>>();
    dim3 grid_sc((Mm + 255) / 256, Bb);
    k_scatter<<<grid_sc, 256>>>(rois, gt, out);
}

// round 9
// speedup vs baseline: 1.5695x; 1.1828x over previous
#include <cuda_runtime.h>

// Problem shapes (fixed by the dataset).
constexpr int Bb = 16;
constexpr int Kk = 128;
constexpr int Nn = 8192;
constexpr int Mm = Nn + Kk;   // 8320
constexpr int Ww = Mm / 32;   // 260 bitmask words per batch

// Output packing: tuple concatenated in return order, all float32.
constexpr size_t OFF_ROIS = 0;
constexpr size_t OFF_LAB  = (size_t)Bb * Mm * 5;
constexpr size_t OFF_TGT  = OFF_LAB + (size_t)Bb * Mm;
constexpr size_t OFF_IW   = OFF_TGT + (size_t)Bb * Mm * 4;
constexpr size_t OFF_OW   = OFF_IW  + (size_t)Bb * Mm * 4;

// Scratch (no allocations allowed -> __device__ globals).
__device__ int      g_assign[Bb * Mm];
__device__ unsigned g_mask[Bb * Ww];

// ---------------------------------------------------------------------------
// Kernel 1: per-roi IoU max/argmax over K gt boxes. 1 roi/thread (max
// occupancy), +1 folded into precomputed x2+1/y2+1 on both sides, single
// clamp (negative ih auto-rejected by the sign of in_ in the comparator),
// division-free comparator inter_k*S_b > bI*S_k (ov = r/(1-r) monotone in
// r = inter/S). Appended-gt self-pairs resolved analytically (ov==1 exactly
// in the reference). Emits focal weights (original order) + fg bitmask.
// ---------------------------------------------------------------------------
__global__ __launch_bounds__(256) void k_iou(const float* __restrict__ rois,
                                             const float* __restrict__ gt,
                                             float* __restrict__ out) {
    const int b = blockIdx.y;
    const int t = threadIdx.x;
    const int m = blockIdx.x * 256 + t;
    const bool valid = (m < Mm);
    const int mm = valid ? m : (Mm - 1);

    __shared__ float4 sc[Kk];                    // gx1, gy1, gx2+1 (-1e30 if zero-area), gy2+1
    __shared__ __align__(16) float ssar[Kk];     // gt area (reference expression)

    const float* gtb = gt + (size_t)b * Kk * 5;
    if (t < Kk) {
        float x1 = gtb[t * 5 + 0], y1 = gtb[t * 5 + 1];
        float x2 = gtb[t * 5 + 2], y2 = gtb[t * 5 + 3];
        float w = x2 - x1 + 1.0f, h = y2 - y1 + 1.0f;
        bool zf = (w == 1.0f) && (h == 1.0f);
        sc[t] = make_float4(x1, y1, zf ? -1e30f : (x2 + 1.0f), y2 + 1.0f);
        ssar[t] = w * h;
    }
    __syncthreads();

    float x1, y1, x2, y2;
    if (mm < Nn) { const float* p = rois + ((size_t)b * Nn + mm) * 5;
                   x1 = p[1]; y1 = p[2]; x2 = p[3]; y2 = p[4]; }
    else         { const float* p = gtb + (size_t)(mm - Nn) * 5;
                   x1 = p[0]; y1 = p[1]; x2 = p[2]; y2 = p[3]; }
    const float aw = x2 - x1 + 1.0f;
    const float ah = y2 - y1 + 1.0f;
    const float aA = aw * ah;
    const float X2p = x2 + 1.0f, Y2p = y2 + 1.0f;

    float bI = 0.0f, bS = 1.0f;
    int arg = 0;

    #pragma unroll 2
    for (int kk = 0; kk < Kk; kk += 4) {
        const float4 sa4 = *(const float4*)&ssar[kk];
        const float sas[4] = {sa4.x, sa4.y, sa4.z, sa4.w};
        #pragma unroll
        for (int j = 0; j < 4; ++j) {
            const int k = kk + j;
            const float4 c = sc[k];
            float iw = fmaxf(fminf(X2p, c.z) - fmaxf(x1, c.x), 0.0f);
            float ih = fminf(Y2p, c.w) - fmaxf(y1, c.y);   // unclamped: ih<0 -> in_<=0 never wins
            float in_ = iw * ih;
            float S = aA + sas[j];
            bool p = in_ * bS > bI * S;
            bI = p ? in_ : bI;
            bS = p ? S : bS;
            arg = p ? k : arg;
        }
    }

    float mo; int a; bool fg;
    if ((aw == 1.0f) && (ah == 1.0f)) {        // zero-area roi (absent in data)
        mo = -1.0f; fg = false; a = 0;
    } else if (m >= Nn) {                      // appended gt: self-IoU == 1 exactly
        mo = 1.0f; fg = true; a = m - Nn;
    } else {
        mo = bI / (bS - bI);                   // one exact div, reference expression
        fg = (mo >= 0.5f);
        a = arg;
    }
    fg = fg && valid;
    const unsigned bal = __ballot_sync(0xffffffffu, fg);
    if (valid) {
        const int idx = b * Mm + m;
        if (fg) g_assign[idx] = a;
        const float om = 1.0f - mo;
        const float w = fg ? om * om : 0.0f;
        const float ow = (w > 0.0f) ? 1.0f : 0.0f;
        ((float4*)(out + OFF_IW))[idx] = make_float4(w, w, w, w);
        ((float4*)(out + OFF_OW))[idx] = make_float4(ow, ow, ow, ow);
        if ((t & 31) == 0) g_mask[b * Ww + (m >> 5)] = bal;   // Mm%32==0: word fully valid
    }
}

// ---------------------------------------------------------------------------
// Kernel 2: fused scan + scatter. Each block redundantly scans the batch's
// 260 mask-word popcounts into smem (cheap: ~30 instrs/thread, L2-resident),
// then scatters rois/labels/targets using recovered dest indices.
// ---------------------------------------------------------------------------
__global__ __launch_bounds__(256) void k_scatter(const float* __restrict__ rois,
                                                 const float* __restrict__ gt,
                                                 float* __restrict__ out) {
    const int b = blockIdx.y;
    const int t = threadIdx.x;
    const int lane = t & 31, wid = t >> 5;

    __shared__ unsigned s_mask[Ww];
    __shared__ int s_off[Ww];
    __shared__ int s_ws[8];

    // --- inline per-batch exclusive scan of word popcounts ---
    const int w0 = 2 * t, w1 = 2 * t + 1;
    unsigned mk0 = 0, mk1 = 0;
    if (w0 < Ww) mk0 = g_mask[b * Ww + w0];
    if (w1 < Ww) mk1 = g_mask[b * Ww + w1];
    const int c0 = __popc(mk0);
    const int s = c0 + __popc(mk1);

    int v = s;
    #pragma unroll
    for (int o = 1; o < 32; o <<= 1) {
        int n = __shfl_up_sync(0xffffffffu, v, o);
        if (lane >= o) v += n;
    }
    if (lane == 31) s_ws[wid] = v;
    __syncthreads();
    if (t < 8) {
        int x = s_ws[t];
        #pragma unroll
        for (int o = 1; o < 8; o <<= 1) {
            int n = __shfl_up_sync(0x000000ffu, x, o);
            if (t >= o) x += n;
        }
        s_ws[t] = x;
    }
    __syncthreads();
    const int excl = v - s + (wid ? s_ws[wid - 1] : 0);
    if (w0 < Ww) { s_off[w0] = excl;      s_mask[w0] = mk0; }
    if (w1 < Ww) { s_off[w1] = excl + c0; s_mask[w1] = mk1; }
    __syncthreads();
    const int tot = s_ws[7];

    // --- scatter ---
    const int m = blockIdx.x * 256 + t;
    if (m >= Mm) return;

    const int word = m >> 5, bit = m & 31;
    const unsigned mask = s_mask[word];
    const int pre = s_off[word] + __popc(mask & ((1u << bit) - 1u));
    const bool fg = (mask >> bit) & 1u;
    const int d = fg ? pre : tot + (m - pre);

    float x1, y1, x2, y2;
    if (m < Nn) {
        const float* r = rois + ((size_t)b * Nn + m) * 5;
        x1 = r[1]; y1 = r[2]; x2 = r[3]; y2 = r[4];
    } else {
        const float* r = gt + ((size_t)b * Kk + (m - Nn)) * 5;
        x1 = r[0]; y1 = r[1]; x2 = r[2]; y2 = r[3];
    }

    float* rb = out + OFF_ROIS + ((size_t)b * Mm + d) * 5;
    rb[0] = (float)b; rb[1] = x1; rb[2] = y1; rb[3] = x2; rb[4] = y2;

    float lab = 0.0f;
    float t0 = 0.0f, t1 = 0.0f, t2 = 0.0f, t3 = 0.0f;
    if (fg) {
        const int a = g_assign[b * Mm + m];
        const float* gb = gt + ((size_t)b * Kk + a) * 5;
        lab = gb[4];                                 // labels in {1..3}
        float ew = x2 - x1 + 1.0f, eh = y2 - y1 + 1.0f;
        float ecx = x1 + 0.5f * ew, ecy = y1 + 0.5f * eh;
        float gw = gb[2] - gb[0] + 1.0f, gh = gb[3] - gb[1] + 1.0f;
        float gcx = gb[0] + 0.5f * gw, gcy = gb[1] + 0.5f * gh;
        t0 = ((gcx - ecx) / ew) / 0.1f;
        t1 = ((gcy - ecy) / eh) / 0.1f;
        t2 = logf(gw / ew) / 0.2f;
        t3 = logf(gh / eh) / 0.2f;
    }
    out[OFF_LAB + (size_t)b * Mm + d] = lab;
    ((float4*)(out + OFF_TGT))[(size_t)b * Mm + d] = make_float4(t0, t1, t2, t3);
}

extern "C" void kernel_launch(void* const* d_in, const int* in_sizes, int n_in,
                              void* d_out, int out_size) {
    const float* rois = (const float*)d_in[0];   // (B, N, 5)
    const float* gt   = (const float*)d_in[1];   // (B, K, 5)
    float* out = (float*)d_out;

    dim3 grid((Mm + 255) / 256, Bb);             // 33 x 16
    k_iou<<<grid, 256>>>(rois, gt, out);
    k_scatter<<<grid, 256>>>(rois, gt, out);
}